// round 10
// baseline (speedup 1.0000x reference)
#include <cuda_runtime.h>
#include <cuda_bf16.h>

// Sparsity_60095182405891: x[64,256,56,56] f32, NCHW.
// mask1: keep top-2 (ties >=) of |x| per 4-channel block.
// mask2: zero kept, keep top-1 (ties >=) of residual per 8-channel block.
// out = x * (mask1 | mask2).
//
// R10: occupancy-without-spills experiment. One thread per 4-channel block
// (4 LDG.128, ~32 regs -> 8 CTA/SM, 64 warps = 2x the converged config);
// the 8-block residual max crosses the warp via one shfl_xor(16):
// lanes 0-15 own channels c0..c0+3, lanes 16-31 own c0+4..c0+7 at the same
// 16 pixels. Isolates "more warps" from R3's spill confound.
// If neutral (my prior: HBM R/W-mix ceiling at ~6.3 TB/s), R6 is final.

#define C_TOT   256
#define HW      3136             // 56*56
#define VEC     (HW / 4)         // 784 float4 per plane
#define WARPS_PER_G8 (VEC / 16)  // 49 warps cover one plane-slab
#define WARPS_PER_IMG (32 * WARPS_PER_G8)   // 1568 = 196 CTAs * 8 warps

__device__ __forceinline__ float second_of_4(float a0, float a1, float a2, float a3) {
    float m01 = fmaxf(a0, a1), n01 = fminf(a0, a1);
    float m23 = fmaxf(a2, a3), n23 = fminf(a2, a3);
    return fmaxf(fminf(m01, m23), fmaxf(n01, n23));
}

__global__ void __launch_bounds__(256)
sparsity_nm_kernel(const float* __restrict__ x, float* __restrict__ out) {
    int lane = threadIdx.x & 31;
    int w    = blockIdx.x * 8 + (threadIdx.x >> 5);   // warp id in image, 0..1567
    int n    = blockIdx.y;

    int g8 = w / WARPS_PER_G8;           // 8-channel group (0..31)
    int pw = w - g8 * WARPS_PER_G8;      // warp's pixel slab (0..48)

    int half = lane >> 4;                // 0: channels c0..c0+3, 1: c0+4..c0+7
    int p    = pw * 16 + (lane & 15);    // float4 index in plane

    int c0 = g8 * 8 + half * 4;
    long base = ((long)(n * C_TOT + c0)) * HW + (long)p * 4;

    const float4* xin = reinterpret_cast<const float4*>(x + base);
    float4*       xo  = reinterpret_cast<float4*>(out + base);

    // 4 independent strided vector loads (channel stride HW floats)
    float4 v[4];
#pragma unroll
    for (int c = 0; c < 4; c++) {
        v[c] = __ldcs(xin + (long)c * (HW / 4));
    }

    float val[4][4];
#pragma unroll
    for (int c = 0; c < 4; c++) {
        val[c][0] = v[c].x; val[c][1] = v[c].y;
        val[c][2] = v[c].z; val[c][3] = v[c].w;
    }

#pragma unroll
    for (int l = 0; l < 4; l++) {
        float a[4];
#pragma unroll
        for (int c = 0; c < 4; c++) a[c] = fabsf(val[c][l]);

        // mask1: top-2 (ties kept) within this 4-channel block
        float thr = second_of_4(a[0], a[1], a[2], a[3]);

        bool  m1[4];
        float r[4];
        float rmax = 0.0f;
#pragma unroll
        for (int c = 0; c < 4; c++) {
            m1[c] = (a[c] >= thr);
            r[c]  = m1[c] ? 0.0f : a[c];
            rmax  = fmaxf(rmax, r[c]);
        }

        // 8-block residual max: combine with partner half-warp lane (same pixel)
        rmax = fmaxf(rmax, __shfl_xor_sync(0xffffffffu, rmax, 16));

        // mask2: top-1 (ties kept) of residual over the 8-block; OR with mask1
#pragma unroll
        for (int c = 0; c < 4; c++) {
            bool keep = m1[c] || (r[c] >= rmax);
            val[c][l] = keep ? val[c][l] : 0.0f;
        }
    }

    // Repack and streaming-store
#pragma unroll
    for (int c = 0; c < 4; c++) {
        float4 o;
        o.x = val[c][0]; o.y = val[c][1]; o.z = val[c][2]; o.w = val[c][3];
        __stcs(xo + (long)c * (HW / 4), o);
    }
}

extern "C" void kernel_launch(void* const* d_in, const int* in_sizes, int n_in,
                              void* d_out, int out_size) {
    const float* x = (const float*)d_in[0];
    float* out = (float*)d_out;
    dim3 grid(WARPS_PER_IMG / 8, 64);   // (196, 64)
    sparsity_nm_kernel<<<grid, 256>>>(x, out);
}